// round 16
// baseline (speedup 1.0000x reference)
#include <cuda_runtime.h>
#include <cstdint>
#include <math.h>

// bayes_55018531062578  (R16: 64-thread block per b, 4 unrolled slots per warp)
//
// out[b] = sigmoid( BEVb[b]-BEVa[b] + (sum_{s<kapa} B[b,k*,s] - A[b,k*,s]) / kapa[b] )
// k*(b,s) = argmax_k ( log_softmax(mean)_k + gumbel(b,s,k) )
// gumbel: JAX partitionable threefry counter mode, bits = o0^o1 of
//   threefry2x32(key=(0,42), (0, i)),  u = bitcast((bits>>9)|0x3f800000)-1
// Fast argmax == argmin_k t_k * (1/w_k),  t_k = -log2(u_k); near-tie
// fallback (rate ~1e-4) replays reference formula (with eps) in fp32.
//
// Layout: warp w (of 2) owns chunks {w, w+2, w+4, w+6}; slot utilization
// E[nch]/(2*E[ceil(nch/2)]) ~= 90% (vs 75% for R15's 4x2). All slots are
// compile-time unrolled with warp-uniform guards; prologue amortized over
// up to 128 samples/warp.

#define EPSF 1e-20f

__device__ __forceinline__ uint32_t rotl32(uint32_t x, int r) {
    return __funnelshift_l(x, x, r);
}

// 4 interleaved threefry2x32 calls, key (0,42), inputs (0, c0+k), k=0..3.
__device__ __forceinline__ void threefry_xor4(uint32_t c0, uint32_t bits[4]) {
    const uint32_t ks0 = 0u;
    const uint32_t ks1 = 42u;
    const uint32_t ks2 = 0x1BD11BDAu ^ 42u;

    uint32_t x0[4], x1[4];
#pragma unroll
    for (int k = 0; k < 4; k++) { x0[k] = ks0; x1[k] = c0 + (uint32_t)k + ks1; }

#define TF_R(r) _Pragma("unroll") \
    for (int k = 0; k < 4; k++) { x0[k] += x1[k]; x1[k] = rotl32(x1[k],(r)) ^ x0[k]; }
#define TF_INJ(i0, i1) _Pragma("unroll") \
    for (int k = 0; k < 4; k++) { x0[k] += (i0); x1[k] += (i1); }

    TF_R(13) TF_R(15) TF_R(26) TF_R(6)
    TF_INJ(ks1, ks2 + 1u)
    TF_R(17) TF_R(29) TF_R(16) TF_R(24)
    TF_INJ(ks2, ks0 + 2u)
    TF_R(13) TF_R(15) TF_R(26) TF_R(6)
    TF_INJ(ks0, ks1 + 3u)
    TF_R(17) TF_R(29) TF_R(16) TF_R(24)
    TF_INJ(ks1, ks2 + 4u)
    TF_R(13) TF_R(15) TF_R(26) TF_R(6)
    TF_INJ(ks2, ks0 + 5u)

#undef TF_R
#undef TF_INJ
#pragma unroll
    for (int k = 0; k < 4; k++) bits[k] = x0[k] ^ x1[k];
}

__device__ __forceinline__ float bits_to_uniform(uint32_t bits) {
    return __uint_as_float((bits >> 9) | 0x3f800000u) - 1.0f;
}

__global__ __launch_bounds__(64, 20)
void bayes_kernel(const float* __restrict__ A,
                  const float* __restrict__ Bm,
                  const float* __restrict__ BEVa,
                  const float* __restrict__ BEVb,
                  const int*   __restrict__ kapa,
                  const float* __restrict__ mean,
                  float* __restrict__ out,
                  int S) {
    const int b    = blockIdx.x;
    const int tid  = threadIdx.x;
    const int warp = tid >> 5;       // 0 or 1
    const int lane = tid & 31;

    __shared__ float red[2];

    const int kap = kapa[b];

    // Warp fully dead iff its first chunk start >= kap (only warp 1, kap<=32).
    if ((warp << 5) >= kap) {
        if (lane == 0) red[warp] = 0.0f;
        return;
    }

    // Prologue (amortized over up to 128 samples/warp): inverse softmax wts.
    const float m0 = mean[0], m1 = mean[1], m2 = mean[2], m3 = mean[3];
    const float mx = fmaxf(fmaxf(m0, m1), fmaxf(m2, m3));
    const float e0 = __expf(m0 - mx), e1 = __expf(m1 - mx);
    const float e2 = __expf(m2 - mx), e3 = __expf(m3 - mx);
    const float iw[4] = {__fdividef(1.0f, e0), __fdividef(1.0f, e1),
                         __fdividef(1.0f, e2), __fdividef(1.0f, e3)};
    const float iwmax = fmaxf(fmaxf(iw[0], iw[1]), fmaxf(iw[2], iw[3]));

    const float* Ab = A  + (size_t)b * 4 * S;
    const float* Bb = Bm + (size_t)b * 4 * S;

    float diff = 0.0f;

#pragma unroll
    for (int j = 0; j < 4; j++) {
        const int c = warp + 2 * j;            // chunk index
        const int cs = c << 5;                 // chunk start
        if (cs < kap) {                        // warp-uniform guard
            const int s = cs + lane;
            const uint32_t base = ((uint32_t)b * (uint32_t)S + (uint32_t)s) * 4u;

            uint32_t bits[4];
            threefry_xor4(base, bits);

            float u[4], q[4];
#pragma unroll
            for (int k = 0; k < 4; k++) {
                u[k] = bits_to_uniform(bits[k]);
                const float t = -__log2f(u[k]);   // u==0 -> +inf, never wins
                q[k] = t * iw[k];
            }

            // argmin with runner-up tracking
            int   kb = 0;
            float best = q[0], second = INFINITY;
            if (q[1] < best) { second = best; best = q[1]; kb = 1; } else second = q[1];
            if (q[2] < best) { second = best; best = q[2]; kb = 2; } else if (q[2] < second) second = q[2];
            if (q[3] < best) { second = best; best = q[3]; kb = 3; } else if (q[3] < second) second = q[3];

            // Error-model gate (~40x safety on fast-path fp error)
            const float thresh = iwmax * 2e-5f + second * 1e-5f;
            if (second - best < thresh) {
                // rare accurate fp32 fallback: exact reference formula
                const float se  = e0 + e1 + e2 + e3;
                const float lse = mx + logf(se);
                const float lg[4] = {m0 - lse, m1 - lse, m2 - lse, m3 - lse};
                float bs = -INFINITY; int kk = 0;
#pragma unroll
                for (int k = 0; k < 4; k++) {
                    const float g  = -logf(-logf(u[k] + EPSF) + EPSF);
                    const float sc = lg[k] + g;
                    if (sc > bs) { bs = sc; kk = k; }
                }
                kb = kk;
            }

            if (s < kap) {
                const size_t off = (size_t)kb * S + s;
                diff += Bb[off] - Ab[off];
            }
        }
    }

    // warp reduction, then 2-warp combine
#pragma unroll
    for (int o = 16; o > 0; o >>= 1)
        diff += __shfl_down_sync(0xffffffffu, diff, o);
    if (lane == 0) red[warp] = diff;

    __syncthreads();

    if (tid == 0) {
        const float tot = red[0] + red[1];
        const float x = BEVb[b] - BEVa[b] + tot / (float)kap;
        out[b] = 1.0f / (1.0f + expf(-x));
    }
}

extern "C" void kernel_launch(void* const* d_in, const int* in_sizes, int n_in,
                              void* d_out, int out_size) {
    // metadata order: outcomeA, outcomeB, BEVa, BEVb, kapa, batch_size, features, mean
    const float* A    = (const float*)d_in[0];
    const float* Bm   = (const float*)d_in[1];
    const float* BEVa = (const float*)d_in[2];
    const float* BEVb = (const float*)d_in[3];
    const int*   kapa = (const int*)  d_in[4];

    // mean is the (only) 4-element input; locate it robustly from the tail
    const float* mean = (const float*)d_in[n_in - 1];
    for (int i = n_in - 1; i >= 5; --i) {
        if (in_sizes[i] == 4) { mean = (const float*)d_in[i]; break; }
    }

    float* out = (float*)d_out;

    const int B = in_sizes[2];                 // 16384
    const int S = in_sizes[0] / (4 * B);       // 256

    bayes_kernel<<<B, 64>>>(A, Bm, BEVa, BEVb, kapa, mean, out, S);
}